// round 13
// baseline (speedup 1.0000x reference)
#include <cuda_runtime.h>
#include <cuda_bf16.h>
#include <cstddef>

// Shapes: user [B=32, U=128, D=256] fp32, image [B=32, I=256, D=256] fp32
// out = concat(user * img_sum[b,1,:], image * user_sum[b,1,:])
//
// FINAL (R11 structure, best measured: 7.71us ncu / 8.67us bench):
// - read-once fused kernel, 24MB minimum HBM traffic
// - grid 256 x 256thr, TX=8: every warp row-segment = one full 128B line
// - all 12 input rows per thread loaded up front (MLP=12) into registers
// - both column sums via one shuffle tree + one smem round + ONE barrier
// - ld.global.nc reads (read-only) + st.global.cs evict-first streaming
//   writes (outputs never re-read; keeps inputs L2-resident across replays)

#define BB 32
#define UU 128
#define II 256
#define DD 256

#define TX 8                 // float4 lanes: 32 floats = 128B per warp row
#define TY 32                // row groups
#define NT (TX * TY)         // 256 threads
#define DCH 32               // d-chunk per CTA
#define NCH (DD / DCH)       // 8
#define GRID (BB * NCH)      // 256
#define NWARPS (NT / 32)     // 8

__device__ __forceinline__ float4 f4add(float4 a, float4 b) {
    return make_float4(a.x + b.x, a.y + b.y, a.z + b.z, a.w + b.w);
}
__device__ __forceinline__ float4 f4mul(float4 a, float4 b) {
    return make_float4(a.x * b.x, a.y * b.y, a.z * b.z, a.w * b.w);
}
__device__ __forceinline__ void f4shfl_acc(float4& a, int m) {
    a.x += __shfl_xor_sync(0xffffffffu, a.x, m);
    a.y += __shfl_xor_sync(0xffffffffu, a.y, m);
    a.z += __shfl_xor_sync(0xffffffffu, a.z, m);
    a.w += __shfl_xor_sync(0xffffffffu, a.w, m);
}
__device__ __forceinline__ float4 ldg_nc(const float4* p) {
    float4 v;
    asm volatile("ld.global.nc.v4.f32 {%0,%1,%2,%3}, [%4];"
                 : "=f"(v.x), "=f"(v.y), "=f"(v.z), "=f"(v.w) : "l"(p));
    return v;
}
__device__ __forceinline__ void stg_cs(float4* p, float4 v) {
    asm volatile("st.global.cs.v4.f32 [%0], {%1,%2,%3,%4};"
                 :: "l"(p), "f"(v.x), "f"(v.y), "f"(v.z), "f"(v.w) : "memory");
}

__global__ __launch_bounds__(NT)
void ExternalInteraction_65609920413984_kernel(
    const float* __restrict__ user,
    const float* __restrict__ img,
    float* __restrict__ out_user,
    float* __restrict__ out_img)
{
    __shared__ float4 wsI[NWARPS][TX];
    __shared__ float4 wsU[NWARPS][TX];

    const int b  = blockIdx.x >> 3;               // / NCH
    const int d0 = (blockIdx.x & (NCH - 1)) * DCH;
    const int tx = threadIdx.x & (TX - 1);
    const int ty = threadIdx.x >> 3;
    const int warp = threadIdx.x >> 5;
    const int lane = threadIdx.x & 31;
    const int d  = d0 + tx * 4;
    const int rs = DD / 4;                        // row stride in float4

    const float4* up = reinterpret_cast<const float4*>(user + (size_t)b * UU * DD + d);
    const float4* ip = reinterpret_cast<const float4*>(img  + (size_t)b * II * DD + d);
    float4* ou = reinterpret_cast<float4*>(out_user + (size_t)b * UU * DD + d);
    float4* oi = reinterpret_cast<float4*>(out_img  + (size_t)b * II * DD + d);

    // ---- Phase A: issue ALL loads up front (12 independent float4 / thread)
    float4 iv[II / TY];   // 8
    float4 uv[UU / TY];   // 4
    #pragma unroll
    for (int k = 0; k < II / TY; k++)
        iv[k] = ldg_nc(ip + (size_t)(ty + k * TY) * rs);
    #pragma unroll
    for (int k = 0; k < UU / TY; k++)
        uv[k] = ldg_nc(up + (size_t)(ty + k * TY) * rs);

    // ---- Phase B: both partial sums from registers
    float4 ai = f4add(f4add(f4add(iv[0], iv[1]), f4add(iv[2], iv[3])),
                      f4add(f4add(iv[4], iv[5]), f4add(iv[6], iv[7])));
    float4 au = f4add(f4add(uv[0], uv[1]), f4add(uv[2], uv[3]));

    // Intra-warp: reduce over the 4 ty-subrows sharing each tx (xor 8, 16)
    f4shfl_acc(ai, 8);  f4shfl_acc(ai, 16);
    f4shfl_acc(au, 8);  f4shfl_acc(au, 16);

    if (lane < TX) { wsI[warp][tx] = ai; wsU[warp][tx] = au; }
    __syncthreads();                       // the ONLY barrier

    // Cross-warp: every thread sums the 8 warp partials (broadcast LDS)
    float4 is = wsI[0][tx];
    float4 us = wsU[0][tx];
    #pragma unroll
    for (int w = 1; w < NWARPS; w++) {
        is = f4add(is, wsI[w][tx]);
        us = f4add(us, wsU[w][tx]);
    }

    // ---- Phase C: all stores straight from registers (streaming, evict-first)
    #pragma unroll
    for (int k = 0; k < UU / TY; k++)
        stg_cs(ou + (size_t)(ty + k * TY) * rs, f4mul(uv[k], is));
    #pragma unroll
    for (int k = 0; k < II / TY; k++)
        stg_cs(oi + (size_t)(ty + k * TY) * rs, f4mul(iv[k], us));
}

extern "C" void kernel_launch(void* const* d_in, const int* in_sizes, int n_in,
                              void* d_out, int out_size)
{
    (void)in_sizes; (void)n_in; (void)out_size;
    const float* user = (const float*)d_in[0];
    const float* img  = (const float*)d_in[1];
    float* out_user = (float*)d_out;
    float* out_img  = (float*)d_out + (size_t)BB * UU * DD;

    ExternalInteraction_65609920413984_kernel
        <<<GRID, NT>>>(user, img, out_user, out_img);
}